// round 8
// baseline (speedup 1.0000x reference)
#include <cuda_runtime.h>
#include <math.h>

#define T_LEN 1024
#define DX    32
#define DZ    64
#define DY    256
#define BB    4
#define NCTA  128
#define NTHR  256
#define ALPHA 0.125f
#define KHPAD 36                 // szfB: padded k-half stride
#define ZROW  (2 * KHPAD)        // 72
#define HROW  288                // shB: 8 y-chunks of 32 padded to 36 slots each

// Packed fp32x2 FMA (Blackwell sm_103a): d = a*b + c elementwise on 64-bit pairs.
__device__ __forceinline__ float2 ffma2(float2 a, float2 b, float2 c) {
    unsigned long long au = *reinterpret_cast<unsigned long long*>(&a);
    unsigned long long bu = *reinterpret_cast<unsigned long long*>(&b);
    unsigned long long cu = *reinterpret_cast<unsigned long long*>(&c);
    unsigned long long du;
    asm("fma.rn.f32x2 %0, %1, %2, %3;" : "=l"(du) : "l"(au), "l"(bu), "l"(cu));
    return *reinterpret_cast<float2*>(&du);
}

__global__ __launch_bounds__(NTHR, 1)
void plrnn_kernel(const float* __restrict__ X,
                  const float* __restrict__ A,
                  const float* __restrict__ W1,   // (dz, dy) row-major
                  const float* __restrict__ W2,   // (dy, dz) row-major
                  const float* __restrict__ h1,
                  const float* __restrict__ h2,
                  float* __restrict__ out)        // (B, T, dx)
{
    __shared__ float szfB[BB][ZROW];   // [b][36*(k>>5) + (k&31)] zf
    __shared__ float shB [BB][HROW];   // [b][36*(y>>5) + (y&31)] hidden

    const int t = threadIdx.x;

    // GEMM1 role (R3-exact): 2 consecutive y, one k-half; partner = lane^1
    const int y0  = 2 * (t >> 1);
    const int kh  = t & 1;
    const int kb  = kh * KHPAD;
    const int ysl = y0 + 4 * (y0 >> 5);          // padded shB slot for y0 (y0,y0+1 contiguous)

    // GEMM2 role: z-pair zp, y-chunk q8; butterfly over the 8 q8 lanes
    const int zp  = t >> 3;                      // 0..31
    const int q8  = t & 7;                       // 0..7
    const int yb  = 36 * q8;                     // padded base of y-chunk [32*q8, +32)

    // state owner after butterfly: (b, z)
    const int b   = q8 >> 1;
    const int z   = 2 * zp + (q8 & 1);
    const int bg  = blockIdx.x * BB + b;
    const int zsl = 36 * (z >> 5) + (z & 31);

    // ---- weights in registers, natural (even,odd) float2 pairs ----
    float2 w2a[16], w2b[16];                     // W2 rows y0/y0+1, this k-half
#pragma unroll
    for (int p = 0; p < 16; ++p) {
        w2a[p] = *reinterpret_cast<const float2*>(&W2[(size_t)y0 * DZ + 32 * kh + 2 * p]);
        w2b[p] = *reinterpret_cast<const float2*>(&W2[(size_t)(y0 + 1) * DZ + 32 * kh + 2 * p]);
    }
    float2 w1a[16], w1b[16];                     // W1 rows 2zp/2zp+1, y in [32*q8, +32)
#pragma unroll
    for (int p = 0; p < 16; ++p) {
        w1a[p] = *reinterpret_cast<const float2*>(&W1[(size_t)(2 * zp) * DY + 32 * q8 + 2 * p]);
        w1b[p] = *reinterpret_cast<const float2*>(&W1[(size_t)(2 * zp + 1) * DY + 32 * q8 + 2 * p]);
    }
    const float2 h2v = *reinterpret_cast<const float2*>(&h2[y0]);
    const float  Az  = A[z];
    const float  h1z = h1[z];

    const float* Xb = X   + (size_t)bg * T_LEN * DX;
    float*       Ob = out + (size_t)bg * T_LEN * DX;

    // ---- z0: first dx dims forced with alpha=1, rest zero ----
    float zcur = 0.0f, x_next = 0.0f;
    if (z < DX) {                                 // warp-uniform (z = 8*warp + ...)
        float x0 = Xb[z];
        zcur   = (x0 != x0) ? 0.0f : x0;          // NaN -> keep 0
        x_next = x0;                               // step-0 forcing reuses X[:,0]
    }

    for (int step = 0; step < T_LEN; ++step) {
        // ---- phase 0: teacher forcing + publish zf (every thread owns one state) ----
        float zf;
        if (z < DX) {
            float x = x_next;
            zf = (x != x) ? zcur : fmaf(ALPHA, x, (1.0f - ALPHA) * zcur);
            if (step + 1 < T_LEN)
                x_next = Xb[(size_t)(step + 1) * DX + z];
        } else {
            zf = zcur;
        }
        szfB[b][zsl] = zf;                        // perfect bank permutation: 1 wf
        __syncthreads();                          // B1: zf ready

        // ---- GEMM1 (R3-exact): (y0,y0+1) x 4 batches over k-half ----
        {
            float2 a0[BB], a1[BB];
#pragma unroll
            for (int bb = 0; bb < BB; ++bb) { a0[bb] = make_float2(0.f, 0.f);
                                              a1[bb] = make_float2(0.f, 0.f); }
#pragma unroll
            for (int j = 0; j < 8; ++j) {
#pragma unroll
                for (int bb = 0; bb < BB; ++bb) {
                    float4 v = *reinterpret_cast<const float4*>(&szfB[bb][kb + 4 * j]);
                    float2 lo = make_float2(v.x, v.y), hi = make_float2(v.z, v.w);
                    a0[bb] = ffma2(w2a[2 * j],     lo, a0[bb]);
                    a0[bb] = ffma2(w2a[2 * j + 1], hi, a0[bb]);
                    a1[bb] = ffma2(w2b[2 * j],     lo, a1[bb]);
                    a1[bb] = ffma2(w2b[2 * j + 1], hi, a1[bb]);
                }
            }
            float s0[BB], s1[BB];
#pragma unroll
            for (int bb = 0; bb < BB; ++bb) {
                s0[bb] = a0[bb].x + a0[bb].y;
                s1[bb] = a1[bb].x + a1[bb].y;
                s0[bb] += __shfl_xor_sync(0xffffffffu, s0[bb], 1);
                s1[bb] += __shfl_xor_sync(0xffffffffu, s1[bb], 1);
            }
            const int bs = kh * 2;                // lane kh stores batches {2kh, 2kh+1}
#pragma unroll
            for (int u = 0; u < 2; ++u) {
                float2 hv;
                hv.x = fmaxf(s0[bs + u] + h2v.x, 0.0f);
                hv.y = fmaxf(s1[bs + u] + h2v.y, 0.0f);
                *reinterpret_cast<float2*>(&shB[bs + u][ysl]) = hv;   // 2-wf min
            }
        }
        __syncthreads();                          // B2: hidden ready

        // ---- GEMM2: partials over own 32-wide y-chunk, all 4 batches, 2 z ----
        float P00, P01, P02, P03, P10, P11, P12, P13;
        {
            float2 c0[BB], c1[BB];
#pragma unroll
            for (int bb = 0; bb < BB; ++bb) { c0[bb] = make_float2(0.f, 0.f);
                                              c1[bb] = make_float2(0.f, 0.f); }
#pragma unroll
            for (int yq = 0; yq < 8; ++yq) {
#pragma unroll
                for (int bb = 0; bb < BB; ++bb) {
                    // 8 distinct bank-quads across the warp: 1 wf per LDS.128
                    float4 hv = *reinterpret_cast<const float4*>(&shB[bb][yb + 4 * yq]);
                    float2 lo = make_float2(hv.x, hv.y), hi = make_float2(hv.z, hv.w);
                    c0[bb] = ffma2(w1a[2 * yq],     lo, c0[bb]);
                    c0[bb] = ffma2(w1a[2 * yq + 1], hi, c0[bb]);
                    c1[bb] = ffma2(w1b[2 * yq],     lo, c1[bb]);
                    c1[bb] = ffma2(w1b[2 * yq + 1], hi, c1[bb]);
                }
            }
            P00 = c0[0].x + c0[0].y;  P01 = c0[1].x + c0[1].y;
            P02 = c0[2].x + c0[2].y;  P03 = c0[3].x + c0[3].y;
            P10 = c1[0].x + c1[0].y;  P11 = c1[1].x + c1[1].y;
            P12 = c1[2].x + c1[2].y;  P13 = c1[3].x + c1[3].y;
        }

        // ---- butterfly combine over the 8 q8 lanes (7 shfls, no barrier) ----
        {
            const bool zodd = (q8 & 1);           // round 1: z-bit
            float K0 = (zodd ? P10 : P00) + __shfl_xor_sync(0xffffffffu, (zodd ? P00 : P10), 1);
            float K1 = (zodd ? P11 : P01) + __shfl_xor_sync(0xffffffffu, (zodd ? P01 : P11), 1);
            float K2 = (zodd ? P12 : P02) + __shfl_xor_sync(0xffffffffu, (zodd ? P02 : P12), 1);
            float K3 = (zodd ? P13 : P03) + __shfl_xor_sync(0xffffffffu, (zodd ? P03 : P13), 1);

            const bool bl = (q8 >> 1) & 1;        // round 2: b low bit
            float Ka = (bl ? K1 : K0) + __shfl_xor_sync(0xffffffffu, (bl ? K0 : K1), 2);
            float Kb = (bl ? K3 : K2) + __shfl_xor_sync(0xffffffffu, (bl ? K2 : K3), 2);

            const bool bh = (q8 >> 2) & 1;        // round 3: b high bit
            float g  = (bh ? Kb : Ka) + __shfl_xor_sync(0xffffffffu, (bh ? Ka : Kb), 4);

            // state update for this thread's (b, z); next iteration publishes it
            float znew = fmaf(Az, zf, g + h1z);
            zcur = znew;
            if (z < DX)
                Ob[(size_t)step * DX + z] = znew;
        }
        // WAR safety: next szfB write happens after next-loop's code preceding B1;
        // GEMM1 reads of this step finished before B2. shB reads (GEMM2, after B2)
        // precede next step's shB writes, which occur after next B1.
    }
}

extern "C" void kernel_launch(void* const* d_in, const int* in_sizes, int n_in,
                              void* d_out, int out_size)
{
    const float* X  = (const float*)d_in[0];   // (512, 1024, 32)
    const float* A  = (const float*)d_in[1];   // (64,)
    const float* W1 = (const float*)d_in[2];   // (64, 256)
    const float* W2 = (const float*)d_in[3];   // (256, 64)
    const float* h1 = (const float*)d_in[4];   // (64,)
    const float* h2 = (const float*)d_in[5];   // (256,)
    plrnn_kernel<<<NCTA, NTHR>>>(X, A, W1, W2, h1, h2, (float*)d_out);
}

// round 9
// speedup vs baseline: 1.5334x; 1.5334x over previous
#include <cuda_runtime.h>
#include <math.h>

#define T_LEN 1024
#define DX    32
#define DZ    64
#define DY    256
#define BB    4
#define NCTA  128
#define NTHR  512
#define ALPHA 0.125f
#define KHPAD 36                 // szfB padded k-half stride (bank-quads disjoint)
#define ZROW  (2 * KHPAD)        // 72
#define HROW  264                // 2*HROW mod 32 == 16 -> G1 STS.32 spans all 32 banks

// Packed fp32x2 FMA (Blackwell sm_103a): d = a*b + c elementwise on 64-bit pairs.
__device__ __forceinline__ float2 ffma2(float2 a, float2 b, float2 c) {
    unsigned long long au = *reinterpret_cast<unsigned long long*>(&a);
    unsigned long long bu = *reinterpret_cast<unsigned long long*>(&b);
    unsigned long long cu = *reinterpret_cast<unsigned long long*>(&c);
    unsigned long long du;
    asm("fma.rn.f32x2 %0, %1, %2, %3;" : "=l"(du) : "l"(au), "l"(bu), "l"(cu));
    return *reinterpret_cast<float2*>(&du);
}

__global__ __launch_bounds__(NTHR, 1)
void plrnn_kernel(const float* __restrict__ X,
                  const float* __restrict__ A,
                  const float* __restrict__ W1,   // (dz, dy) row-major
                  const float* __restrict__ W2,   // (dy, dz) row-major
                  const float* __restrict__ h1,
                  const float* __restrict__ h2,
                  float* __restrict__ out)        // (B, T, dx)
{
    __shared__ float szfB[BB][ZROW];    // [b][36*(k>>5)+(k&31)] zf
    __shared__ float shB [BB][HROW];    // [b][y] hidden
    __shared__ float sPart[8][BB][DZ];  // [ychunk][b][z] GEMM2 partials

    const int t = threadIdx.x;

    // ---- GEMM1 role: 1 y, one k-half, all 4 batches; partner = lane^1 ----
    const int y1 = t >> 1;              // 0..255
    const int kh = t & 1;
    const int kb = kh * KHPAD;

    // ---- GEMM2 role: 1 z, one 32-wide y chunk (warp-uniform), all 4 batches ----
    const int w  = t >> 5;              // warp id 0..15
    const int g  = w & 7;               // y chunk
    const int z2 = ((w >> 3) << 5) | (t & 31);  // z = 32*(w>>3) + lane

    // ---- state owner role (threads 0..255): (b, z) ----
    const int z   = t & 63;
    const int b   = (t >> 6) & 3;
    const int bg  = blockIdx.x * BB + b;
    const int zsl = ((z >> 5) * KHPAD) + (z & 31);
    const bool owner = (t < 256);

    // ---- weights in registers (natural (even,odd) float2 pairs, no dup) ----
    float2 w2r[16];                     // W2[y1][32kh .. 32kh+31]
#pragma unroll
    for (int p = 0; p < 16; ++p)
        w2r[p] = *reinterpret_cast<const float2*>(&W2[(size_t)y1 * DZ + 32 * kh + 2 * p]);
    float2 w1r[16];                     // W1[z2][32g .. 32g+31]
#pragma unroll
    for (int p = 0; p < 16; ++p)
        w1r[p] = *reinterpret_cast<const float2*>(&W1[(size_t)z2 * DY + 32 * g + 2 * p]);

    const float h2y = h2[y1];
    const float Az  = A[z];
    const float h1z = h1[z];

    const float* Xb = X   + (size_t)bg * T_LEN * DX;
    float*       Ob = out + (size_t)bg * T_LEN * DX;

    // ---- z0: first dx dims forced with alpha=1, rest zero (owners only) ----
    float zcur = 0.0f, x_next = 0.0f;
    if (owner && z < DX) {
        float x0 = Xb[z];
        zcur   = (x0 != x0) ? 0.0f : x0;   // NaN -> keep 0
        x_next = x0;                        // step-0 forcing reuses X[:,0]
    }

    for (int step = 0; step < T_LEN; ++step) {
        // ---- phase 0: teacher forcing + publish zf (owners) ----
        if (owner) {
            float zf;
            if (z < DX) {                   // warp-uniform (z spans 32/warp)
                float x = x_next;
                zf = (x != x) ? zcur : fmaf(ALPHA, x, (1.0f - ALPHA) * zcur);
                if (step + 1 < T_LEN)
                    x_next = Xb[(size_t)(step + 1) * DX + z];
            } else {
                zf = zcur;
            }
            zcur = zf;                      // value used by A*zf in the update
            szfB[b][zsl] = zf;              // bank permutation: 1 wf
        }
        __syncthreads();                    // B1: zf ready

        // ---- GEMM1: S[bb] = W2[y1, khalf] . zf[khalf, bb] ----
        {
            float2 a[BB];
#pragma unroll
            for (int bb = 0; bb < BB; ++bb) a[bb] = make_float2(0.f, 0.f);
#pragma unroll
            for (int j = 0; j < 8; ++j) {
#pragma unroll
                for (int bb = 0; bb < BB; ++bb) {
                    // 2 distinct 16B addrs/warp on disjoint bank-quads: 1 wf
                    float4 v = *reinterpret_cast<const float4*>(&szfB[bb][kb + 4 * j]);
                    a[bb] = ffma2(w2r[2 * j],     make_float2(v.x, v.y), a[bb]);
                    a[bb] = ffma2(w2r[2 * j + 1], make_float2(v.z, v.w), a[bb]);
                }
            }
            float S0 = a[0].x + a[0].y, S1 = a[1].x + a[1].y;
            float S2 = a[2].x + a[2].y, S3 = a[3].x + a[3].y;
            // payload-split single-round combine (2 independent shfls):
            // lane kh finalizes batches {2kh, 2kh+1}
            float v1 = kh ? S0 : S2;        // what the partner needs (slot 1)
            float v2 = kh ? S1 : S3;        // slot 2
            float r1 = __shfl_xor_sync(0xffffffffu, v1, 1);
            float r2 = __shfl_xor_sync(0xffffffffu, v2, 1);
            float F1 = (kh ? S2 : S0) + r1; // batch 2kh
            float F2 = (kh ? S3 : S1) + r2; // batch 2kh+1
            // STS.32 x2: banks {y%32} U {16+y%32} across the warp: 1 wf each
            shB[2 * kh    ][y1] = fmaxf(F1 + h2y, 0.0f);
            shB[2 * kh + 1][y1] = fmaxf(F2 + h2y, 0.0f);
        }
        __syncthreads();                    // B2: hidden ready

        // ---- GEMM2: part[g][bb][z2] = W1[z2, 32g:+32] . hidden[32g:+32, bb] ----
        {
            float2 c[BB];
#pragma unroll
            for (int bb = 0; bb < BB; ++bb) c[bb] = make_float2(0.f, 0.f);
#pragma unroll
            for (int yq = 0; yq < 8; ++yq) {
#pragma unroll
                for (int bb = 0; bb < BB; ++bb) {
                    // warp-uniform address -> broadcast, 1 wf
                    float4 hv = *reinterpret_cast<const float4*>(&shB[bb][32 * g + 4 * yq]);
                    c[bb] = ffma2(w1r[2 * yq],     make_float2(hv.x, hv.y), c[bb]);
                    c[bb] = ffma2(w1r[2 * yq + 1], make_float2(hv.z, hv.w), c[bb]);
                }
            }
#pragma unroll
            for (int bb = 0; bb < BB; ++bb)
                sPart[g][bb][z2] = c[bb].x + c[bb].y;   // lane-linear: 1 wf
        }
        __syncthreads();                    // B3: partials ready

        // ---- reduce 8 chunks + state update + output (owners) ----
        if (owner) {
            float s = 0.0f;
#pragma unroll
            for (int gg = 0; gg < 8; ++gg) s += sPart[gg][b][z];   // 1 wf each
            float znew = fmaf(Az, zcur, s + h1z);
            zcur = znew;
            if (z < DX)
                Ob[(size_t)step * DX + z] = znew;   // coalesced
        }
    }
}

extern "C" void kernel_launch(void* const* d_in, const int* in_sizes, int n_in,
                              void* d_out, int out_size)
{
    const float* X  = (const float*)d_in[0];   // (512, 1024, 32)
    const float* A  = (const float*)d_in[1];   // (64,)
    const float* W1 = (const float*)d_in[2];   // (64, 256)
    const float* W2 = (const float*)d_in[3];   // (256, 64)
    const float* h1 = (const float*)d_in[4];   // (64,)
    const float* h2 = (const float*)d_in[5];   // (256,)
    plrnn_kernel<<<NCTA, NTHR>>>(X, A, W1, W2, h1, h2, (float*)d_out);
}